// round 9
// baseline (speedup 1.0000x reference)
#include <cuda_runtime.h>
#include <cuda_fp16.h>
#include <math.h>

#define NB    512
#define NK    64
#define NC    2048
#define BDIM  128
#define SPLIT 2                       // CTAs per batch row
#define CHPB  (NC / SPLIT)            // 1024 channels per CTA
#define CPT   (CHPB / BDIM)           // 8 channels per thread
#define NPAIR (CPT / 2)               // 4 packed pairs per thread

typedef unsigned long long ull;

__device__ __forceinline__ ull pack2(float lo, float hi) {
    ull r;
    asm("mov.b64 %0, {%1, %2};" : "=l"(r) : "f"(lo), "f"(hi));
    return r;
}
__device__ __forceinline__ void unpack2(ull v, float& lo, float& hi) {
    asm("mov.b64 {%0, %1}, %2;" : "=f"(lo), "=f"(hi) : "l"(v));
}
__device__ __forceinline__ ull fma2(ull a, ull b, ull c) {
    ull r;
    asm("fma.rn.f32x2 %0, %1, %2, %3;" : "=l"(r) : "l"(a), "l"(b), "l"(c));
    return r;
}
// both exps of a packed pair via ONE MUFU op (ex2.approx.f16x2)
__device__ __forceinline__ ull exp2_pair_f16(float q0, float q1) {
    unsigned int h2, e2;
    asm("cvt.rn.f16x2.f32 %0, %1, %2;" : "=r"(h2) : "f"(q1), "f"(q0)); // lo=q0, hi=q1
    asm("ex2.approx.f16x2 %0, %1;" : "=r"(e2) : "r"(h2));
    float e0, e1;
    asm("{\n\t"
        ".reg .b16 l, h;\n\t"
        "mov.b32 {l, h}, %2;\n\t"
        "cvt.f32.f16 %0, l;\n\t"
        "cvt.f32.f16 %1, h;\n\t"
        "}" : "=f"(e0), "=f"(e1) : "r"(e2));
    return pack2(e0, e1);
}

__global__ __launch_bounds__(BDIM)
void mixture_kernel(const float* __restrict__ mo,
                    const float* __restrict__ X,
                    float* __restrict__ out) {
    // 64B coefficient record per k: [A B | C D | E F | W pad] -> four LDS.128
    // (dup-packed f32x2 halves, conflict-free broadcast)
    __shared__ __align__(16) ulonglong2 sCo[NK][4];

    const int b    = blockIdx.x / SPLIT;
    const int part = blockIdx.x % SPLIT;
    const int tid  = threadIdx.x;

    // --- per-(b,k) coefficient precompute (first 64 threads) ---
    if (tid < NK) {
        const float* p = mo + ((size_t)b * NK + tid) * 6;
        float w  = p[0];
        float m1 = p[1];
        float m2 = p[2];
        float s1 = p[3];
        float s2 = p[4];
        float r  = p[5];

        float omr2 = 1.0f - r * r;
        float inv  = 1.0f / omr2;
        float is1  = 1.0f / s1;
        float is2  = 1.0f / s2;

        const float L2E = 1.4426950408889634f;   // log2(e)
        float a  = -0.5f * inv * is1 * is1 * L2E;
        float bb =  r    * inv * is1 * is2 * L2E;
        float cc = -0.5f * inv * is2 * is2 * L2E;

        float d = -(2.0f * a  * m1 + bb * m2);
        float e = -(2.0f * cc * m2 + bb * m1);
        // W kept SEPARATE (not folded into exponent) so the fp16 exponent
        // stays small for dominant terms -> fp16 rounding error stays ~5e-4
        float f = a * m1 * m1 + bb * m1 * m2 + cc * m2 * m2;
        float W = w * is1 * is2 * rsqrtf(omr2) * 0.15915494309189535f;

        sCo[tid][0] = make_ulonglong2(pack2(a,  a),  pack2(bb, bb));
        sCo[tid][1] = make_ulonglong2(pack2(cc, cc), pack2(d,  d));
        sCo[tid][2] = make_ulonglong2(pack2(e,  e),  pack2(f,  f));
        sCo[tid][3] = make_ulonglong2(pack2(W,  W),  0ull);
    }
    __syncthreads();

    // --- per-thread packed channel state (4 pairs = 8 channels) ---
    const int base = part * CHPB;
    const float2* Xb = reinterpret_cast<const float2*>(X) + (size_t)b * NC + base;

    ull xx[NPAIR], yy[NPAIR], acc[NPAIR];
    #pragma unroll
    for (int p = 0; p < NPAIR; p++) {
        float2 v0 = Xb[tid + (2 * p)     * BDIM];
        float2 v1 = Xb[tid + (2 * p + 1) * BDIM];
        xx[p]  = pack2(v0.x, v1.x);
        yy[p]  = pack2(v0.y, v1.y);
        acc[p] = 0ull;
    }

    // per element: 3 FFMA2 + 0.5 MUFU(f16x2) + cvt ops + 0.5 FFMA2 accumulate
    #pragma unroll 4
    for (int k = 0; k < NK; k++) {
        const ulonglong2 c01 = sCo[k][0];
        const ulonglong2 c23 = sCo[k][1];
        const ulonglong2 c45 = sCo[k][2];
        const ulonglong2 c6  = sCo[k][3];
        const ull AA = c01.x, BB = c01.y;
        const ull CC = c23.x, DD = c23.y;
        const ull EE = c45.x, FF = c45.y;
        const ull WW = c6.x;

        #pragma unroll
        for (int p = 0; p < NPAIR; p++) {
            ull u = fma2(AA, xx[p], fma2(BB, yy[p], DD));
            ull v = fma2(CC, yy[p], EE);
            ull q = fma2(u, xx[p], fma2(v, yy[p], FF));
            float q0, q1;
            unpack2(q, q0, q1);
            ull ee = exp2_pair_f16(q0, q1);
            acc[p] = fma2(WW, ee, acc[p]);
        }
    }

    float* ob = out + (size_t)b * NC + base;
    #pragma unroll
    for (int p = 0; p < NPAIR; p++) {
        float a0, a1;
        unpack2(acc[p], a0, a1);
        ob[tid + (2 * p)     * BDIM] = a0;
        ob[tid + (2 * p + 1) * BDIM] = a1;
    }
}

extern "C" void kernel_launch(void* const* d_in, const int* in_sizes, int n_in,
                              void* d_out, int out_size) {
    const float* mo = (const float*)d_in[0];   // model_out: (512, 64, 6) f32
    const float* X  = (const float*)d_in[1];   // X:         (512, 2048, 2) f32
    float* out      = (float*)d_out;           // out:       (512, 2048) f32
    (void)in_sizes; (void)n_in; (void)out_size;

    mixture_kernel<<<NB * SPLIT, BDIM>>>(mo, X, out);
}

// round 10
// speedup vs baseline: 1.1877x; 1.1877x over previous
#include <cuda_runtime.h>
#include <math.h>

#define NB    512
#define NK    64
#define NC    2048
#define BDIM  128
#define SPLIT 2                       // CTAs per batch row
#define CHPB  (NC / SPLIT)            // 1024 channels per CTA
#define CPT   (CHPB / BDIM)           // 8 channels per thread
#define NPAIR (CPT / 2)               // 4 packed pairs per thread

typedef unsigned long long ull;

__device__ __forceinline__ ull pack2(float lo, float hi) {
    ull r;
    asm("mov.b64 %0, {%1, %2};" : "=l"(r) : "f"(lo), "f"(hi));
    return r;
}
__device__ __forceinline__ void unpack2(ull v, float& lo, float& hi) {
    asm("mov.b64 {%0, %1}, %2;" : "=f"(lo), "=f"(hi) : "l"(v));
}
__device__ __forceinline__ ull fma2(ull a, ull b, ull c) {
    ull r;
    asm("fma.rn.f32x2 %0, %1, %2, %3;" : "=l"(r) : "l"(a), "l"(b), "l"(c));
    return r;
}
__device__ __forceinline__ ull add2(ull a, ull b) {
    ull r;
    asm("add.rn.f32x2 %0, %1, %2;" : "=l"(r) : "l"(a), "l"(b));
    return r;
}
__device__ __forceinline__ float ex2a(float x) {
    float r;
    asm("ex2.approx.ftz.f32 %0, %1;" : "=f"(r) : "f"(x));
    return r;
}
__device__ __forceinline__ float lg2a(float x) {
    float r;
    asm("lg2.approx.ftz.f32 %0, %1;" : "=f"(r) : "f"(x));
    return r;
}

__global__ __launch_bounds__(BDIM, 7)
void mixture_kernel(const float* __restrict__ mo,
                    const float* __restrict__ X,
                    float* __restrict__ out) {
    // 64B coefficient record per k: [A B | C D | E F | pad] -> three LDS.128
    __shared__ __align__(16) ulonglong2 sCo[NK][4];

    const int b    = blockIdx.x / SPLIT;
    const int part = blockIdx.x % SPLIT;
    const int tid  = threadIdx.x;

    // --- per-(b,k) coefficient precompute (first 64 threads) ---
    if (tid < NK) {
        const float* p = mo + ((size_t)b * NK + tid) * 6;
        float w  = p[0];
        float m1 = p[1];
        float m2 = p[2];
        float s1 = p[3];
        float s2 = p[4];
        float r  = p[5];

        float omr2 = 1.0f - r * r;
        float inv  = 1.0f / omr2;
        float is1  = 1.0f / s1;
        float is2  = 1.0f / s2;

        const float L2E = 1.4426950408889634f;   // log2(e)
        float a  = -0.5f * inv * is1 * is1 * L2E;
        float bb =  r    * inv * is1 * is2 * L2E;
        float cc = -0.5f * inv * is2 * is2 * L2E;

        float d = -(2.0f * a  * m1 + bb * m2);
        float e = -(2.0f * cc * m2 + bb * m1);
        // fold weight/normalizer into exponent: W * 2^q == 2^(q + log2 W)
        float W = w * is1 * is2 * rsqrtf(omr2) * 0.15915494309189535f;
        float f = a * m1 * m1 + bb * m1 * m2 + cc * m2 * m2 + lg2a(W);

        sCo[tid][0] = make_ulonglong2(pack2(a,  a),  pack2(bb, bb));
        sCo[tid][1] = make_ulonglong2(pack2(cc, cc), pack2(d,  d));
        sCo[tid][2] = make_ulonglong2(pack2(e,  e),  pack2(f,  f));
    }
    __syncthreads();

    // --- per-thread packed channel state (4 pairs = 8 channels) ---
    const int base = part * CHPB;
    const float2* Xb = reinterpret_cast<const float2*>(X) + (size_t)b * NC + base;

    ull xx[NPAIR], yy[NPAIR], acc[NPAIR];
    #pragma unroll
    for (int p = 0; p < NPAIR; p++) {
        float2 v0 = Xb[tid + (2 * p)     * BDIM];
        float2 v1 = Xb[tid + (2 * p + 1) * BDIM];
        xx[p]  = pack2(v0.x, v1.x);
        yy[p]  = pack2(v0.y, v1.y);
        acc[p] = 0ull;
    }

    // --- two k's fused per iteration: 8 independent quad->ex2->acc chains ---
    #pragma unroll 2
    for (int k2 = 0; k2 < NK; k2 += 2) {
        const ulonglong2 a01 = sCo[k2][0];
        const ulonglong2 a23 = sCo[k2][1];
        const ulonglong2 a45 = sCo[k2][2];
        const ulonglong2 b01 = sCo[k2 + 1][0];
        const ulonglong2 b23 = sCo[k2 + 1][1];
        const ulonglong2 b45 = sCo[k2 + 1][2];

        ull qa[NPAIR], qb[NPAIR];
        #pragma unroll
        for (int p = 0; p < NPAIR; p++) {
            ull ua = fma2(a01.x, xx[p], fma2(a01.y, yy[p], a23.y));
            ull va = fma2(a23.x, yy[p], a45.x);
            qa[p]  = fma2(ua, xx[p], fma2(va, yy[p], a45.y));

            ull ub = fma2(b01.x, xx[p], fma2(b01.y, yy[p], b23.y));
            ull vb = fma2(b23.x, yy[p], b45.x);
            qb[p]  = fma2(ub, xx[p], fma2(vb, yy[p], b45.y));
        }
        #pragma unroll
        for (int p = 0; p < NPAIR; p++) {
            float qa0, qa1, qb0, qb1;
            unpack2(qa[p], qa0, qa1);
            unpack2(qb[p], qb0, qb1);
            ull ea = pack2(ex2a(qa0), ex2a(qa1));
            ull eb = pack2(ex2a(qb0), ex2a(qb1));
            acc[p] = add2(add2(ea, eb), acc[p]);
        }
    }

    float* ob = out + (size_t)b * NC + base;
    #pragma unroll
    for (int p = 0; p < NPAIR; p++) {
        float a0, a1;
        unpack2(acc[p], a0, a1);
        ob[tid + (2 * p)     * BDIM] = a0;
        ob[tid + (2 * p + 1) * BDIM] = a1;
    }
}

extern "C" void kernel_launch(void* const* d_in, const int* in_sizes, int n_in,
                              void* d_out, int out_size) {
    const float* mo = (const float*)d_in[0];   // model_out: (512, 64, 6) f32
    const float* X  = (const float*)d_in[1];   // X:         (512, 2048, 2) f32
    float* out      = (float*)d_out;           // out:       (512, 2048) f32
    (void)in_sizes; (void)n_in; (void)out_size;

    mixture_kernel<<<NB * SPLIT, BDIM>>>(mo, X, out);
}